// round 15
// baseline (speedup 1.0000x reference)
#include <cuda_runtime.h>
#include <cuda_fp16.h>
#include <climits>

#define MAX_NODES 100000
#define MAX_EDGES 3200000
#define CHANNELS  64
#define NPB       256                      // nodes per bucket
#define NB_MAX    ((MAX_NODES + NPB - 1) / NPB)   // 391
#define BCAP      9216                     // bucket capacity (mean 8192, +11 sigma)
#define EBLOCKS   2048                     // edge blocks in K1
#define S_CAP     2048                     // K1 smem staging tile

// Static scratch (runtime allocation forbidden). Zero-initialized at load
// except g_row_min; every launch restores state before it ends (graph-replay
// safe): g_bktcnt reset by K2, g_ovf_cnt/g_row_min reset by fixup.
__device__ __half   g_Wth[(size_t)MAX_NODES * CHANNELS];   // 12.8 MB fp16 W^T
__device__ unsigned g_bkt[(size_t)NB_MAX * BCAP];          // 14.4 MB packed edges
__device__ int      g_bktcnt[NB_MAX];
__device__ int      g_ovf_row[MAX_EDGES];
__device__ int      g_ovf_col[MAX_EDGES];
__device__ int      g_ovf_cnt;
__device__ int      g_row_min = INT_MAX;

// ---------------------------------------------------------------------------
// K1: bucket-partition edges (no per-edge global atomics) + W transpose,
//     roles interleaved. Packed entry: (row mod 256) << 17 | col  (col < 2^17).
// ---------------------------------------------------------------------------
__global__ void __launch_bounds__(512) build_kernel(const float* __restrict__ W,
                                                    const void* __restrict__ edge,
                                                    int N, int E, int chunk) {
    const int G  = gridDim.x;
    const int bx = blockIdx.x;
    const long long lo = (long long)bx * EBLOCKS / G;
    const long long hi = (long long)(bx + 1) * EBLOCKS / G;

    if (hi == lo) {
        // ---- transpose role: W [64, N] -> g_Wth [N, 64] fp16 ----
        __shared__ float tile[64][33];
        int tb = bx - (int)hi;                 // 0 .. (G-EBLOCKS-1)
        int n0 = tb * 32;
        int tx = threadIdx.x & 31, ty = threadIdx.x >> 5;   // ty 0..15
        #pragma unroll
        for (int j = 0; j < 64; j += 16)
            tile[j + ty][tx] = W[(size_t)(j + ty) * N + n0 + tx];
        __syncthreads();
        #pragma unroll
        for (int j = 0; j < 32; j += 16) {
            int n = j + ty;
            int c = tx * 2;
            __half2 h = __floats2half2_rn(tile[c][n], tile[c + 1][n]);
            *reinterpret_cast<__half2*>(g_Wth + (size_t)(n0 + n) * CHANNELS + c) = h;
        }
        return;
    }

    // ---- edge role ----
    __shared__ int s_row[S_CAP], s_col[S_CAP];
    __shared__ int s_hist[NB_MAX], s_base[NB_MAX], s_cur[NB_MAX];

    // dtype sniff: int64 buffers have all-zero odd 32-bit words for idx < 2^31
    const int* words = (const int*)edge;
    int w = 2 * threadIdx.x + 1;
    int nz = (w < 2 * E && words[w] != 0) ? 1 : 0;
    const int is64 = __syncthreads_or(nz) ? 0 : 1;

    const int eb = (int)lo;
    const int e0 = eb * chunk;
    const int e1 = min(e0 + chunk, E);
    int v = INT_MAX;

    for (int t0 = e0; t0 < e1; t0 += S_CAP) {
        int tlen = min(S_CAP, e1 - t0);
        for (int i = threadIdx.x; i < NB_MAX; i += 512) s_hist[i] = 0;
        __syncthreads();
        // pass A: stage + per-bucket histogram (smem atomics only)
        for (int k = threadIdx.x; k < tlen; k += 512) {
            int r, c;
            if (is64) {
                r = (int)((const long long*)edge)[t0 + k];
                c = (int)((const long long*)edge)[(long long)E + t0 + k];
            } else {
                r = ((const int*)edge)[t0 + k];
                c = ((const int*)edge)[E + t0 + k];
            }
            s_row[k] = r;
            s_col[k] = c;
            v = min(v, r);
            atomicAdd(&s_hist[r >> 8], 1);
        }
        __syncthreads();
        // reserve: ONE global atomic per touched bucket per tile
        for (int i = threadIdx.x; i < NB_MAX; i += 512) {
            int h = s_hist[i];
            s_cur[i]  = 0;
            s_base[i] = h ? atomicAdd(&g_bktcnt[i], h) : 0;
        }
        __syncthreads();
        // pass B: write packed entries to block-contiguous bucket runs
        for (int k = threadIdx.x; k < tlen; k += 512) {
            int r = s_row[k], c = s_col[k];
            int bkt = r >> 8;
            int rank = atomicAdd(&s_cur[bkt], 1);
            long long slot = (long long)s_base[bkt] + rank;
            if (slot < BCAP) {
                g_bkt[(size_t)bkt * BCAP + slot] =
                    ((unsigned)(r & 255) << 17) | (unsigned)c;
            } else {                                   // cold exactness path
                int o = atomicAdd(&g_ovf_cnt, 1);
                g_ovf_row[o] = r;
                g_ovf_col[o] = c;
            }
        }
        __syncthreads();
    }
    #pragma unroll
    for (int o = 16; o; o >>= 1)
        v = min(v, __shfl_xor_sync(0xffffffffu, v, o));
    if ((threadIdx.x & 31) == 0)
        atomicMin(&g_row_min, v);
}

// ---------------------------------------------------------------------------
// K2: per bucket — smem counting-sort by node, then warp-per-node gather
//     (cols from smem, W rows from L2), bias folded, streaming store.
//     Extra blocks write bias-only tail rows [N - rmin, N).
// ---------------------------------------------------------------------------
__global__ void __launch_bounds__(512) bucket_gather_kernel(const float* __restrict__ b,
                                                            float* __restrict__ out,
                                                            int N, int NBr) {
    const int rmin = g_row_min;
    const int bx = blockIdx.x;

    if (bx >= NBr) {
        // ---- bias-only tail role ----
        int e = bx - NBr;
        long long start_o = (long long)N - rmin + (long long)e * 512;
        if (start_o >= N) return;
        for (int idx = threadIdx.x; idx < 512 * 16; idx += 512) {
            int ro = idx >> 4, sub = idx & 15;
            long long o = start_o + ro;
            if (o < N) {
                float4 bb = __ldg(reinterpret_cast<const float4*>(b) + sub);
                reinterpret_cast<float4*>(out + o * CHANNELS)[sub] = bb;
            }
        }
        return;
    }

    __shared__ int s_sorted[BCAP];
    __shared__ int s_hist[NPB], s_off[NPB], s_cur[NPB], s_scan[NPB];

    const int cnt = min(g_bktcnt[bx], BCAP);
    const unsigned* bktp = g_bkt + (size_t)bx * BCAP;

    if (threadIdx.x < NPB) s_hist[threadIdx.x] = 0;
    __syncthreads();
    // pass 1: histogram by node-in-bucket
    for (int i = threadIdx.x; i < cnt; i += 512)
        atomicAdd(&s_hist[bktp[i] >> 17], 1);
    __syncthreads();
    // exclusive scan over 256 counters
    if (threadIdx.x < NPB) s_scan[threadIdx.x] = s_hist[threadIdx.x];
    __syncthreads();
    for (int of = 1; of < NPB; of <<= 1) {
        int add = (threadIdx.x < NPB && threadIdx.x >= of) ? s_scan[threadIdx.x - of] : 0;
        __syncthreads();
        if (threadIdx.x < NPB) s_scan[threadIdx.x] += add;
        __syncthreads();
    }
    if (threadIdx.x < NPB) {
        int excl = s_scan[threadIdx.x] - s_hist[threadIdx.x];
        s_off[threadIdx.x] = excl;
        s_cur[threadIdx.x] = excl;
    }
    __syncthreads();
    // pass 2: scatter cols into node-sorted smem array
    for (int i = threadIdx.x; i < cnt; i += 512) {
        unsigned vv = bktp[i];
        int pos = atomicAdd(&s_cur[vv >> 17], 1);
        s_sorted[pos] = (int)(vv & 0x1FFFFu);
    }
    __syncthreads();
    if (threadIdx.x == 0) g_bktcnt[bx] = 0;    // reset for next replay

    // gather: 16 warps x 16 nodes each
    int wid = threadIdx.x >> 5, lane = threadIdx.x & 31;
    int grp = lane >> 3, sub = lane & 7;
    for (int nl = wid; nl < NPB; nl += 16) {
        int raw = bx * NPB + nl;
        if (raw >= N) break;
        long long orow = (long long)raw - rmin;
        int deg   = s_hist[nl];
        int start = s_off[nl];

        float acc[8] = {0.f, 0.f, 0.f, 0.f, 0.f, 0.f, 0.f, 0.f};
        #pragma unroll 4
        for (int j = start + grp; j < start + deg; j += 4) {
            int c = s_sorted[j];
            uint4 wv = __ldcg(reinterpret_cast<const uint4*>(g_Wth + (size_t)c * CHANNELS) + sub);
            const __half2* h = reinterpret_cast<const __half2*>(&wv);
            #pragma unroll
            for (int k = 0; k < 4; k++) {
                float2 f = __half22float2(h[k]);
                acc[2 * k]     += f.x;
                acc[2 * k + 1] += f.y;
            }
        }
        #pragma unroll
        for (int k = 0; k < 8; k++) {
            acc[k] += __shfl_down_sync(0xffffffffu, acc[k], 16);
            acc[k] += __shfl_down_sync(0xffffffffu, acc[k], 8);
        }
        if (grp == 0 && orow >= 0) {
            float4 b0 = __ldg(reinterpret_cast<const float4*>(b) + sub * 2);
            float4 b1 = __ldg(reinterpret_cast<const float4*>(b) + sub * 2 + 1);
            float4 o0 = make_float4(acc[0] + b0.x, acc[1] + b0.y, acc[2] + b0.z, acc[3] + b0.w);
            float4 o1 = make_float4(acc[4] + b1.x, acc[5] + b1.y, acc[6] + b1.z, acc[7] + b1.w);
            float4* dst = reinterpret_cast<float4*>(out + orow * CHANNELS);
            __stcs(dst + sub * 2,     o0);
            __stcs(dst + sub * 2 + 1, o1);
        }
    }
}

// ---------------------------------------------------------------------------
// K3: fixup — fold overflow edges exactly (zero iterations normally), then
//     reset global state for the next replay.
// ---------------------------------------------------------------------------
__global__ void fixup_kernel(float* __restrict__ out) {
    const int cnt  = g_ovf_cnt;
    const int rmin = g_row_min;
    long long total = (long long)cnt * 16;
    for (long long t = threadIdx.x; t < total; t += blockDim.x) {
        int e   = (int)(t >> 4);
        int sub = (int)(t & 15);
        int r = g_ovf_row[e] - rmin;
        int c = g_ovf_col[e];
        uint2 wv = *reinterpret_cast<const uint2*>(g_Wth + (size_t)c * CHANNELS + sub * 4);
        float2 f0 = __half22float2(*reinterpret_cast<__half2*>(&wv.x));
        float2 f1 = __half22float2(*reinterpret_cast<__half2*>(&wv.y));
        float* dst = out + (size_t)r * CHANNELS + sub * 4;
        asm volatile("red.global.add.v4.f32 [%0], {%1, %2, %3, %4};"
                     :: "l"(dst), "f"(f0.x), "f"(f0.y), "f"(f1.x), "f"(f1.y)
                     : "memory");
    }
    __syncthreads();
    if (threadIdx.x == 0) {
        g_ovf_cnt = 0;
        g_row_min = INT_MAX;
    }
}

// ---------------------------------------------------------------------------
extern "C" void kernel_launch(void* const* d_in, const int* in_sizes, int n_in,
                              void* d_out, int out_size) {
    const void*  edge = d_in[0];
    const float* W    = (const float*)d_in[1];
    const float* b    = (const float*)d_in[2];
    float*       out  = (float*)d_out;

    const int E = in_sizes[0] / 2;
    const int C = in_sizes[2];             // 64
    const int N = in_sizes[1] / C;         // 100000
    const int chunk = (E + EBLOCKS - 1) / EBLOCKS;
    const int NBr   = (N + NPB - 1) / NPB;           // 391

    // K1: bucket partition + transpose (interleaved roles)
    build_kernel<<<EBLOCKS + N / 32, 512>>>(W, edge, N, E, chunk);

    // K2: per-bucket sort + gather, plus bias-only tail blocks
    bucket_gather_kernel<<<NBr + 196, 512>>>(b, out, N, NBr);

    // K3: overflow fold + state reset
    fixup_kernel<<<1, 512>>>(out);
}